// round 7
// baseline (speedup 1.0000x reference)
#include <cuda_runtime.h>

// PerturbedTopK: x (64,196) f32, noise (64,500,196) f32.
// out[b,k,d] = mean_n [ sorted(top49_idx(x_b + 0.05*noise_bn))[k] == d ].
//
// Key structure: SIGMA=0.05 is small, so every row's 49-of-196 threshold is
// within ~0.03 of the batch threshold of x_b alone. A tiny seed kernel finds
// T_b per batch; the main kernel (1 row/warp, 28 regs, occ ~76%) starts its
// exact count==49 search at T_b and converges in ~3 evals using exact
// boundary-jump steps (pivot := min(selected) or pred(max(unselected)) via
// REDUX on monotonic keys) for |c-49|<=3, Newton (slope ~1/62) otherwise,
// bracket-escape -> bisection. Cap 16 -> exact MSB radix fallback with
// index-order tie-break. Seed quality cannot affect correctness.

#define BATCH 64
#define NSAMP 500
#define DIM   196
#define TOPK  49
#define SIGMA 0.05f

#define OUTN  (BATCH * TOPK * DIM)
#define FULLM 0xffffffffu
#define NEGBIG (-3.402823466e38f)

__device__ float g_Tb[BATCH];

__device__ __forceinline__ unsigned f2key(float v) {
    unsigned u = __float_as_uint(v);
    return u ^ ((unsigned)((int)u >> 31) | 0x80000000u);
}
__device__ __forceinline__ float key2f(unsigned k) {
    unsigned u = (k & 0x80000000u) ? (k ^ 0x80000000u) : ~k;
    return __uint_as_float(u);
}
// 0xFFFFFFFF if a > b else 0 (single SASS FSET).
__device__ __forceinline__ unsigned fgt(float a, float b) {
    unsigned r;
    asm("set.gt.u32.f32 %0, %1, %2;" : "=r"(r) : "f"(a), "f"(b));
    return r;
}

__device__ __forceinline__ unsigned minsel_key(const float val[7], float piv) {
    unsigned mk = 0xFFFFFFFFu;
    #pragma unroll
    for (int j = 0; j < 7; j++)
        mk = min(mk, (val[j] > piv) ? f2key(val[j]) : 0xFFFFFFFFu);
    return __reduce_min_sync(FULLM, mk);
}
__device__ __forceinline__ unsigned maxunsel_key(const float val[7], float piv) {
    unsigned Mk = 0u;
    #pragma unroll
    for (int j = 0; j < 7; j++)
        Mk = max(Mk, (val[j] > piv) ? 0u : f2key(val[j]));
    return __reduce_max_sync(FULLM, Mk);
}

// ---- seed: one warp per batch; boundary-jump toward count==49 on x_b ----
__global__ void seed_kernel(const float* __restrict__ x) {
    const int b = blockIdx.x;
    const int lane = threadIdx.x;
    float val[7];
    #pragma unroll
    for (int j = 0; j < 7; j++) {
        const int d = j * 32 + lane;
        val[j] = (d < DIM) ? x[b * DIM + d] : NEGBIG;
    }
    float piv = 0.674f;
    #pragma unroll 1
    for (int it = 0; it < 40; ++it) {
        unsigned a = 0;
        #pragma unroll
        for (int j = 0; j < 7; j++) a += fgt(val[j], piv);
        const int c = -(int)__reduce_add_sync(FULLM, (int)a);
        if (c == TOPK) break;
        piv = (c > TOPK) ? key2f(minsel_key(val, piv))
                         : key2f(maxunsel_key(val, piv) - 1u);
    }
    if (lane == 0) g_Tb[b] = piv;   // hint only; any value is safe
}

// Rank-and-accumulate for tie-free threshold T (exactly TOPK strictly above).
__device__ __forceinline__ void emit(const float val[7], float T,
                                     float* __restrict__ outb,
                                     int lane, unsigned lt, float invn) {
    int base = 0;
    #pragma unroll
    for (int j = 0; j < 7; j++) {
        const int d = j * 32 + lane;
        const bool s = val[j] > T;
        const unsigned mb = __ballot_sync(FULLM, s);
        if (s) {
            const int rank = base + __popc(mb & lt);
            atomicAdd(outb + rank * DIM + d, invn);
        }
        base += __popc(mb);
    }
}

// Exact MSB radix select + emit with index-order tie-break (cold path).
__device__ void radix_emit(const float val[7], float* __restrict__ outb,
                           int lane, unsigned lt, float invn) {
    unsigned actm = (6 * 32 + lane < DIM) ? 0x7Fu : 0x3Fu;
    int k = TOPK, matching = DIM, s = 0;
    unsigned P = 0u;
    #pragma unroll 1
    for (int bit = 31; bit >= 0; --bit) {
        const unsigned m = 1u << bit;
        int c = 0;
        #pragma unroll
        for (int j = 0; j < 7; j++)
            c += (((actm >> j) & 1u) && (f2key(val[j]) & m)) ? 1 : 0;
        c = __reduce_add_sync(FULLM, c);
        if (c >= k) {
            P |= m; matching = c;
            #pragma unroll
            for (int j = 0; j < 7; j++)
                if (!(f2key(val[j]) & m)) actm &= ~(1u << j);
        } else {
            k -= c; matching -= c;
            #pragma unroll
            for (int j = 0; j < 7; j++)
                if (f2key(val[j]) & m) actm &= ~(1u << j);
        }
        s = bit;
        if (matching == k) break;
    }
    const unsigned Ph = P >> s;
    int gtb = 0, eqb = 0;
    #pragma unroll
    for (int j = 0; j < 7; j++) {
        const int d = j * 32 + lane;
        const bool gt = (d < DIM) && ((f2key(val[j]) >> s) > Ph);
        const bool eq = ((actm >> j) & 1u) != 0u;
        const unsigned mg = __ballot_sync(FULLM, gt);
        const unsigned me = __ballot_sync(FULLM, eq);
        const int gtp = gtb + __popc(mg & lt);
        const int eqp = eqb + __popc(me & lt);
        if (gt || (eq && eqp < k)) {
            const int rank = gtp + min(eqp, k);
            atomicAdd(outb + rank * DIM + d, invn);
        }
        gtb += __popc(mg);
        eqb += __popc(me);
    }
}

__global__ __launch_bounds__(128)
void ptopk_kernel(const float* __restrict__ x,
                  const float* __restrict__ noise,
                  float* __restrict__ out) {
    const int warp = threadIdx.x >> 5;
    const int lane = threadIdx.x & 31;
    const int b    = blockIdx.y;
    const int rib  = blockIdx.x * 4 + warp;   // row in batch, exactly [0,500)

    const float* __restrict__ xr = x + b * DIM;
    const float* __restrict__ nr = noise + ((size_t)b * NSAMP + rib) * DIM;
    const unsigned lt = (1u << lane) - 1u;
    const float invn = 1.0f / (float)NSAMP;
    float* __restrict__ outb = out + b * (TOPK * DIM);

    float val[7];
    #pragma unroll
    for (int j = 0; j < 7; j++) {
        const int d = j * 32 + lane;
        val[j] = (d < DIM) ? fmaf(nr[d], SIGMA, xr[d]) : NEGBIG;
    }

    // ---- seeded exact threshold search ----
    float piv = g_Tb[b];
    float lo = -4.0f, hi = 4.0f;
    float T = 0.0f;
    int found = 0;

    #pragma unroll 1
    for (int it = 0; it < 16; ++it) {
        unsigned a = 0;
        #pragma unroll
        for (int j = 0; j < 7; j++) a += fgt(val[j], piv);   // -1 per hit
        const int c = -(int)__reduce_add_sync(FULLM, (int)a);
        if (c == TOPK) { T = piv; found = 1; break; }
        const bool g = (c > TOPK);
        lo = g ? piv : lo;
        hi = g ? hi  : piv;
        const int dd = c - TOPK;
        float p;
        if (dd > 0 && dd <= 3) {
            p = key2f(minsel_key(val, piv));          // removes >=1
        } else if (dd < 0 && dd >= -3) {
            p = key2f(maxunsel_key(val, piv) - 1u);   // adds >=1
        } else {
            p = fmaf((float)dd, 0.0161f, piv);        // Newton, slope ~ n*phi
        }
        if (!(p > lo && p < hi)) p = 0.5f * (lo + hi);
        piv = p;
    }

    if (found) emit(val, T, outb, lane, lt, invn);
    else       radix_emit(val, outb, lane, lt, invn);
}

extern "C" void kernel_launch(void* const* d_in, const int* in_sizes, int n_in,
                              void* d_out, int out_size) {
    const float* x     = (const float*)d_in[0];
    const float* noise = (const float*)d_in[1];
    if (n_in >= 2 && in_sizes[0] > in_sizes[1]) {
        x     = (const float*)d_in[1];
        noise = (const float*)d_in[0];
    }
    float* out = (float*)d_out;

    cudaMemsetAsync(out, 0, (size_t)OUTN * sizeof(float));
    seed_kernel<<<BATCH, 32>>>(x);
    dim3 grid(125, BATCH, 1);   // 125*4 = 500 rows per batch, no guard
    ptopk_kernel<<<grid, 128>>>(x, noise, out);
}

// round 8
// speedup vs baseline: 1.0828x; 1.0828x over previous
#include <cuda_runtime.h>

// PerturbedTopK: x (64,196) f32, noise (64,500,196) f32.
// out[b,k,d] = mean_n [ sorted(top49_idx(x_b + 0.05*noise_bn))[k] == d ].
//
// Integer-key boundary-jump select. A prep kernel (64 blocks) zeros the
// output AND computes per-batch seed threshold T_b from x alone (SIGMA is
// small, so each row's 49th-largest sits within ~1 count of T_b).
// Main kernel (1 row/warp, key domain): one count at K(T_b), then exact
// boundary jumps — c>49: Kthr=min(selected) [removes >=1];
// c<49: Kthr=max(unselected)-1 [adds >=1] — each verified by recount.
// Exit only on verified count==49 (tie-free selection); tie-skip or cap ->
// exact MSB radix fallback with index-order tie-break. Ranks by ascending
// index via ballot prefix sums; atomicAdd(1/500).

#define BATCH 64
#define NSAMP 500
#define DIM   196
#define TOPK  49
#define SIGMA 0.05f

#define OUTN  (BATCH * TOPK * DIM)
#define FULLM 0xffffffffu
#define NEGBIG (-3.402823466e38f)

__device__ float g_Tb[BATCH];

__device__ __forceinline__ unsigned f2key(float v) {
    unsigned u = __float_as_uint(v);
    return u ^ ((unsigned)((int)u >> 31) | 0x80000000u);
}
__device__ __forceinline__ float key2f(unsigned k) {
    unsigned u = (k & 0x80000000u) ? (k ^ 0x80000000u) : ~k;
    return __uint_as_float(u);
}
// 0xFFFFFFFF if a > b else 0 (single SASS instruction).
__device__ __forceinline__ unsigned fgt(float a, float b) {
    unsigned r;
    asm("set.gt.u32.f32 %0, %1, %2;" : "=r"(r) : "f"(a), "f"(b));
    return r;
}
__device__ __forceinline__ unsigned ugt(unsigned a, unsigned b) {
    unsigned r;
    asm("set.gt.u32.u32 %0, %1, %2;" : "=r"(r) : "r"(a), "r"(b));
    return r;
}

// ---- prep: zero output (warps 1-7) + per-batch seed from x (warp 0) ----
__global__ __launch_bounds__(256)
void prep_kernel(const float* __restrict__ x, float* __restrict__ out) {
    const int b = blockIdx.x;
    const int tid = threadIdx.x;

    if (tid >= 32) {
        float4* ob = reinterpret_cast<float4*>(out + (size_t)b * (TOPK * DIM));
        const float4 z = make_float4(0.f, 0.f, 0.f, 0.f);
        for (int i = tid - 32; i < (TOPK * DIM) / 4; i += 224) ob[i] = z;
        return;
    }

    const int lane = tid;
    float val[7];
    #pragma unroll
    for (int j = 0; j < 7; j++) {
        const int d = j * 32 + lane;
        val[j] = (d < DIM) ? x[b * DIM + d] : NEGBIG;
    }
    float piv = 0.674f;
    #pragma unroll 1
    for (int it = 0; it < 40; ++it) {
        unsigned a = 0;
        #pragma unroll
        for (int j = 0; j < 7; j++) a += fgt(val[j], piv);
        const int c = -(int)__reduce_add_sync(FULLM, (int)a);
        if (c == TOPK) break;
        if (c > TOPK) {
            unsigned mk = 0xFFFFFFFFu;
            #pragma unroll
            for (int j = 0; j < 7; j++)
                mk = min(mk, (val[j] > piv) ? f2key(val[j]) : 0xFFFFFFFFu);
            piv = key2f(__reduce_min_sync(FULLM, mk));
        } else {
            unsigned Mk = 0u;
            #pragma unroll
            for (int j = 0; j < 7; j++)
                Mk = max(Mk, (val[j] > piv) ? 0u : f2key(val[j]));
            piv = key2f(__reduce_max_sync(FULLM, Mk) - 1u);
        }
    }
    if (lane == 0) g_Tb[b] = piv;   // hint only; any value is safe
}

// Exact MSB radix select + emit with index-order tie-break (cold path).
__device__ void radix_emit(const unsigned key[7], float* __restrict__ outb,
                           int lane, unsigned lt, float invn) {
    unsigned actm = (6 * 32 + lane < DIM) ? 0x7Fu : 0x3Fu;
    int k = TOPK, matching = DIM, s = 0;
    unsigned P = 0u;
    #pragma unroll 1
    for (int bit = 31; bit >= 0; --bit) {
        const unsigned m = 1u << bit;
        int c = 0;
        #pragma unroll
        for (int j = 0; j < 7; j++)
            c += (((actm >> j) & 1u) && (key[j] & m)) ? 1 : 0;
        c = __reduce_add_sync(FULLM, c);
        if (c >= k) {
            P |= m; matching = c;
            #pragma unroll
            for (int j = 0; j < 7; j++)
                if (!(key[j] & m)) actm &= ~(1u << j);
        } else {
            k -= c; matching -= c;
            #pragma unroll
            for (int j = 0; j < 7; j++)
                if (key[j] & m) actm &= ~(1u << j);
        }
        s = bit;
        if (matching == k) break;
    }
    const unsigned Ph = P >> s;
    int gtb = 0, eqb = 0;
    #pragma unroll
    for (int j = 0; j < 7; j++) {
        const int d = j * 32 + lane;
        const bool gt = (d < DIM) && ((key[j] >> s) > Ph);
        const bool eq = ((actm >> j) & 1u) != 0u;
        const unsigned mg = __ballot_sync(FULLM, gt);
        const unsigned me = __ballot_sync(FULLM, eq);
        const int gtp = gtb + __popc(mg & lt);
        const int eqp = eqb + __popc(me & lt);
        if (gt || (eq && eqp < k)) {
            const int rank = gtp + min(eqp, k);
            atomicAdd(outb + rank * DIM + d, invn);
        }
        gtb += __popc(mg);
        eqb += __popc(me);
    }
}

__global__ __launch_bounds__(128)
void ptopk_kernel(const float* __restrict__ x,
                  const float* __restrict__ noise,
                  float* __restrict__ out) {
    const int warp = threadIdx.x >> 5;
    const int lane = threadIdx.x & 31;
    const int b    = blockIdx.y;
    const int rib  = blockIdx.x * 4 + warp;   // row in batch, exactly [0,500)

    const float* __restrict__ xr = x + b * DIM;
    const float* __restrict__ nr = noise + ((size_t)b * NSAMP + rib) * DIM;
    const unsigned lt = (1u << lane) - 1u;
    const float invn = 1.0f / (float)NSAMP;
    float* __restrict__ outb = out + b * (TOPK * DIM);

    // Load and convert to monotonic integer keys. Padding -> key 0.
    unsigned key[7];
    #pragma unroll
    for (int j = 0; j < 7; j++) {
        const int d = j * 32 + lane;
        key[j] = (d < DIM) ? f2key(fmaf(nr[d], SIGMA, xr[d])) : 0u;
    }

    // ---- boundary-jump select in key domain ----
    unsigned Kthr = f2key(g_Tb[b]);
    unsigned a = 0;
    #pragma unroll
    for (int j = 0; j < 7; j++) a += ugt(key[j], Kthr);     // -1 per hit
    int c = -(int)__reduce_add_sync(FULLM, (int)a);

    #pragma unroll 1
    for (int it = 0; it < 12 && c != TOPK; ++it) {
        if (c > TOPK) {
            unsigned mk = 0xFFFFFFFFu;                      // min selected key
            #pragma unroll
            for (int j = 0; j < 7; j++)
                mk = min(mk, (key[j] > Kthr) ? key[j] : 0xFFFFFFFFu);
            Kthr = __reduce_min_sync(FULLM, mk);            // removes >=1
        } else {
            unsigned Mk = 0u;                               // max unselected key
            #pragma unroll
            for (int j = 0; j < 7; j++)
                Mk = max(Mk, (key[j] > Kthr) ? 0u : key[j]);
            Kthr = __reduce_max_sync(FULLM, Mk) - 1u;       // adds >=1
        }
        unsigned a2 = 0;
        #pragma unroll
        for (int j = 0; j < 7; j++) a2 += ugt(key[j], Kthr);
        c = -(int)__reduce_add_sync(FULLM, (int)a2);        // verify
    }

    if (c == TOPK) {
        // Exactly TOPK keys strictly above Kthr: tie-free. Rank by index.
        int base = 0;
        #pragma unroll
        for (int j = 0; j < 7; j++) {
            const int d = j * 32 + lane;
            const bool s = key[j] > Kthr;
            const unsigned mb = __ballot_sync(FULLM, s);
            if (s) {
                const int rank = base + __popc(mb & lt);
                atomicAdd(outb + rank * DIM + d, invn);
            }
            base += __popc(mb);
        }
        return;
    }
    radix_emit(key, outb, lane, lt, invn);
}

extern "C" void kernel_launch(void* const* d_in, const int* in_sizes, int n_in,
                              void* d_out, int out_size) {
    const float* x     = (const float*)d_in[0];
    const float* noise = (const float*)d_in[1];
    if (n_in >= 2 && in_sizes[0] > in_sizes[1]) {
        x     = (const float*)d_in[1];
        noise = (const float*)d_in[0];
    }
    float* out = (float*)d_out;

    prep_kernel<<<BATCH, 256>>>(x, out);
    dim3 grid(125, BATCH, 1);   // 125*4 = 500 rows per batch, no guard
    ptopk_kernel<<<grid, 128>>>(x, noise, out);
}